// round 16
// baseline (speedup 1.0000x reference)
#include <cuda_runtime.h>
#include <cuda_bf16.h>
#include <cuda_fp16.h>
#include <cstdint>

// ---------------- problem constants ----------------
#define NROWS   32768        // B*BARS*BEATS*FRAC
#define KF      940          // input features (10*2*47)
#define KPAD    960          // K padded to 30 x 32
#define NOUT    100          // linear out
#define K2PAD   112          // padded K for gemm2 (7 x 16)
#define NSEQ_R  1024         // bars LSTM sequences
#define BEATS_OUT_ELEMS (32768 * 16)
#define BARS_OUT_OFF    BEATS_OUT_ELEMS
#define SSTR    40           // smem row stride in b16 elems (80B, 16B-aligned)
#define XGS     66           // gates smem row stride (floats, even)

// gemm1 (BM=64) smem layout, in __half elems
#define XELE    (64 * SSTR)          // 2560
#define WOFF    XELE                 // W region offset
#define BUFE    (XELE + 128 * SSTR)  // 7680 elems per buffer
#define BUFB    (BUFE * 2)           // 15360 bytes

typedef unsigned int u32;

// ---------------- scratch ----------------
__device__ __half g_Whf[128 * KPAD];     // linear weight fp16 (permuted)
__device__ __half g_Wbh[64 * K2PAD];     // beats wih fp16 (padded)
__device__ float g_gb[64];
// Xlin as fp16, row stride K2PAD; pad cols [100,112) never written -> stay 0
__device__ __half g_Xh[(size_t)NROWS * K2PAD];

// ---------------- fast activations ----------------
__device__ __forceinline__ float tanha_(float x) {
    float y;
    asm("tanh.approx.f32 %0, %1;" : "=f"(y) : "f"(x));
    return y;
}
__device__ __forceinline__ float sig_(float x) {
    return fmaf(tanha_(0.5f * x), 0.5f, 0.5f);
}

// ---------------- K0: permute weights (fp16, 4/thread), beats weights ------
__global__ void prep_kernel(const float* __restrict__ lin_w,
                            const float* __restrict__ b_wih,
                            const float* __restrict__ b_bih,
                            const float* __restrict__ b_bhh) {
    const int NW4 = 128 * KPAD / 4;   // 30720
    int idx = blockIdx.x * blockDim.x + threadIdx.x;
    if (idx < NW4) {
        int base = idx * 4;
        int o  = base / KPAD;
        int m0 = base % KPAD;
        __half h[4];
#pragma unroll
        for (int e = 0; e < 4; e++) {
            int m = m0 + e;
            float v = 0.0f;
            if (o < NOUT && m < KF) {
                int c10 = m / 94;
                int r   = m % 94;
                int c2  = r / 47;
                int c47 = r % 47;
                v = lin_w[o * KF + c10 * 94 + c47 * 2 + c2];
            }
            h[e] = __float2half_rn(v);
        }
        *(uint2*)(g_Whf + base) = *(uint2*)h;
    } else if (idx < NW4 + 64 * K2PAD) {
        int j = idx - NW4;
        int n = j / K2PAD;
        int k = j % K2PAD;
        float v = (k < NOUT) ? b_wih[n * NOUT + k] : 0.0f;
        g_Wbh[j] = __float2half_rn(v);
    } else if (idx < NW4 + 64 * K2PAD + 64) {
        int j = idx - NW4 - 64 * K2PAD;
        g_gb[j] = b_bih[j] + b_bhh[j];
    }
}

// ---------------- mma / async helpers ----------------
__device__ __forceinline__ void ldsm4(u32& r0, u32& r1, u32& r2, u32& r3,
                                      u32 addr) {
    asm volatile("ldmatrix.sync.aligned.m8n8.x4.shared.b16 {%0,%1,%2,%3},[%4];"
                 : "=r"(r0), "=r"(r1), "=r"(r2), "=r"(r3) : "r"(addr));
}
__device__ __forceinline__ void ldsm2(u32& r0, u32& r1, u32 addr) {
    asm volatile("ldmatrix.sync.aligned.m8n8.x2.shared.b16 {%0,%1},[%2];"
                 : "=r"(r0), "=r"(r1) : "r"(addr));
}
__device__ __forceinline__ void mma_f16(float* c, const u32* a, const u32* b) {
    asm volatile(
        "mma.sync.aligned.m16n8k16.row.col.f32.f16.f16.f32 "
        "{%0,%1,%2,%3},{%4,%5,%6,%7},{%8,%9},{%0,%1,%2,%3};"
        : "+f"(c[0]), "+f"(c[1]), "+f"(c[2]), "+f"(c[3])
        : "r"(a[0]), "r"(a[1]), "r"(a[2]), "r"(a[3]), "r"(b[0]), "r"(b[1]));
}
__device__ __forceinline__ void cp16(u32 saddr, const void* gptr) {
    asm volatile("cp.async.ca.shared.global [%0], [%1], 16;"
                 :: "r"(saddr), "l"(gptr) : "memory");
}
__device__ __forceinline__ void cp_commit() {
    asm volatile("cp.async.commit_group;" ::: "memory");
}
__device__ __forceinline__ void cp_wait0() {
    asm volatile("cp.async.wait_group 0;" ::: "memory");
}

// ---------------- K1: Xlin = relu(X @ W^T + b), BM=64 fp16 mma -------------
// 512 CTAs, 30KB smem, 3 CTAs/SM target. W via cp.async (no reg staging),
// X via regs with fp32->fp16 convert. Warp grid: wm=w&3 (16 rows, mf=1),
// wn=w>>2 (64 cols; wn1 trims to 5 nf) -> SMSP-balanced trim.
__global__ __launch_bounds__(256, 3)
void gemm1_kernel(const float* __restrict__ X, const float* __restrict__ lin_b) {
    __shared__ __align__(16) __half smem[2 * BUFE];   // 30720 B

    const int tid  = threadIdx.x;
    const int row0 = blockIdx.x * 64;

    // X loader: row lr, 8 floats at lq
    const int lr = tid >> 2;
    const int lq = (tid & 3) * 8;
    const float* xrow = X + (size_t)(row0 + lr) * KF + lq;
    const int xsoff = lr * SSTR + lq;

    // W loader: row wr, 16 halves at wq via 2x cp.async
    const int wr = tid >> 1;
    const int wq = (tid & 1) * 16;
    const __half* wsrc = g_Whf + wr * KPAD + wq;
    const int wsoff = WOFF + wr * SSTR + wq;

    // ldmatrix lane geometry
    const int lane = tid & 31;
    const int w    = tid >> 5;
    const int wm   = w & 3;       // 16-row slice
    const int wn   = w >> 2;      // 64-col half
    const int NF   = wn ? 5 : 8;
    const int dra  = ((lane >> 3) & 1) * 8 + (lane & 7);
    const int dca  = (lane >> 4) * 8;
    const int aoff = (wm * 16 + dra) * SSTR + dca;
    const int l2   = lane & 15;
    const int boff = WOFF + (wn * 64 + (l2 & 7)) * SSTR + (l2 >> 3) * 8;

    const u32 sbase = (u32)__cvta_generic_to_shared(smem);

    float acc[8][4];
#pragma unroll
    for (int b = 0; b < 8; b++)
#pragma unroll
        for (int c = 0; c < 4; c++) acc[b][c] = 0.0f;

    float xv[8];
    auto load_x = [&](int K0) {
#pragma unroll
        for (int j = 0; j < 2; j++) {
            int kb = K0 + lq + j * 4;
            if (kb + 3 < KF) {
                float4 v = *(const float4*)(xrow + K0 + j * 4);
                xv[j * 4 + 0] = v.x; xv[j * 4 + 1] = v.y;
                xv[j * 4 + 2] = v.z; xv[j * 4 + 3] = v.w;
            } else {
#pragma unroll
                for (int e = 0; e < 4; e++)
                    xv[j * 4 + e] = (kb + e < KF) ? xrow[K0 + j * 4 + e] : 0.0f;
            }
        }
    };
    auto store_x = [&](int buf) {
        u32 hw[4];
#pragma unroll
        for (int p = 0; p < 4; p++) {
            __half2 h = __floats2half2_rn(xv[2 * p], xv[2 * p + 1]);
            hw[p] = *(u32*)&h;
        }
        *(uint4*)(smem + buf * BUFE + xsoff) = make_uint4(hw[0], hw[1], hw[2], hw[3]);
    };
    auto copy_w = [&](int K0, int buf) {
        u32 dst = sbase + (u32)(buf * BUFB + wsoff * 2);
        cp16(dst, wsrc + K0);
        cp16(dst + 16, wsrc + K0 + 8);
        cp_commit();
    };

    // prologue: tile0 -> buf0, stage tile1 X
    load_x(0);
    store_x(0);
    copy_w(0, 0);
    load_x(32);
    cp_wait0();
    __syncthreads();

    for (int it = 0; it < 30; ++it) {
        if (it + 1 < 30) {
            store_x((it + 1) & 1);
            copy_w((it + 1) * 32, (it + 1) & 1);
            if (it + 2 < 30) load_x((it + 2) * 32);
        }

        const u32 cb = sbase + (u32)((it & 1) * BUFB);
#pragma unroll
        for (int kf = 0; kf < 32; kf += 16) {
            u32 af[4];
            u32 bf[8][2];
            ldsm4(af[0], af[1], af[2], af[3], cb + (u32)(aoff + kf) * 2u);
#pragma unroll
            for (int nf = 0; nf < 8; nf++)
                if (nf < NF) {
                    u32 eb = (u32)(boff + nf * 8 * SSTR + kf) * 2u;
                    ldsm2(bf[nf][0], bf[nf][1], cb + eb);
                }
#pragma unroll
            for (int nf = 0; nf < 8; nf++)
                if (nf < NF)
                    mma_f16(acc[nf], af, bf[nf]);
        }

        if (it + 1 < 30) cp_wait0();
        __syncthreads();
    }

    // epilogue: relu + bias, fp16, cols < 100
    const int g  = lane >> 2;
    const int t4 = lane & 3;
#pragma unroll
    for (int nf = 0; nf < 8; nf++)
        if (nf < NF) {
            int col = wn * 64 + nf * 8 + t4 * 2;
            if (col < NOUT) {
                float b0 = __ldg(lin_b + col), b1 = __ldg(lin_b + col + 1);
                int r1 = row0 + wm * 16 + g;
                float v0 = fmaxf(acc[nf][0] + b0, 0.0f);
                float v1 = fmaxf(acc[nf][1] + b1, 0.0f);
                float v2 = fmaxf(acc[nf][2] + b0, 0.0f);
                float v3 = fmaxf(acc[nf][3] + b1, 0.0f);
                *(__half2*)(g_Xh + (size_t)r1 * K2PAD + col) =
                    __floats2half2_rn(v0, v1);
                *(__half2*)(g_Xh + (size_t)(r1 + 8) * K2PAD + col) =
                    __floats2half2_rn(v2, v3);
            }
        }
}

// ---------------- K2: fused gates GEMM + beats LSTM (R12 best) -------------
__global__ __launch_bounds__(256)
void gemm2_beats(const float* __restrict__ whh, float* __restrict__ out) {
    __shared__ float sXG[128 * XGS];   // 33.8 KB

    const int tid  = threadIdx.x;
    const int lane = tid & 31;
    const int w    = tid >> 5;
    const int wm   = w & 3;
    const int wn   = w >> 2;
    const int g    = lane >> 2;
    const int t4   = lane & 3;
    const int rloc = wm * 32;
    const int row0 = blockIdx.x * 128 + rloc;

    float acc[2][4][4];
#pragma unroll
    for (int a = 0; a < 2; a++)
#pragma unroll
        for (int b = 0; b < 4; b++)
#pragma unroll
            for (int c = 0; c < 4; c++) acc[a][b][c] = 0.0f;

#pragma unroll
    for (int kc = 0; kc < 7; kc++) {
        const int k0 = kc * 16 + t4 * 2;
        u32 af[2][4], bf[4][2];
#pragma unroll
        for (int mf = 0; mf < 2; mf++) {
            size_t base = (size_t)(row0 + mf * 16 + g) * K2PAD + k0;
            af[mf][0] = *(const u32*)(g_Xh + base);
            af[mf][1] = *(const u32*)(g_Xh + base + 8 * K2PAD);
            af[mf][2] = *(const u32*)(g_Xh + base + 8);
            af[mf][3] = *(const u32*)(g_Xh + base + 8 * K2PAD + 8);
        }
#pragma unroll
        for (int nf = 0; nf < 4; nf++) {
            int nbase = (wn * 32 + nf * 8 + g) * K2PAD + k0;
            bf[nf][0] = *(const u32*)(g_Wbh + nbase);
            bf[nf][1] = *(const u32*)(g_Wbh + nbase + 8);
        }
#pragma unroll
        for (int mf = 0; mf < 2; mf++)
#pragma unroll
            for (int nf = 0; nf < 4; nf++)
                mma_f16(acc[mf][nf], af[mf], bf[nf]);
    }

    // gates + bias -> smem
#pragma unroll
    for (int mf = 0; mf < 2; mf++)
#pragma unroll
        for (int nf = 0; nf < 4; nf++) {
            int col = wn * 32 + nf * 8 + t4 * 2;
            float b0 = g_gb[col], b1 = g_gb[col + 1];
            int r = rloc + mf * 16 + g;
            *(float2*)(sXG + r * XGS + col) =
                make_float2(acc[mf][nf][0] + b0, acc[mf][nf][1] + b1);
            *(float2*)(sXG + (r + 8) * XGS + col) =
                make_float2(acc[mf][nf][2] + b0, acc[mf][nf][3] + b1);
        }
    __syncthreads();

    // ---- beats LSTM: warp w handles local seqs 2w, 2w+1 interleaved ----
    float w0[16], w1[16];
#pragma unroll
    for (int j = 0; j < 16; j++) {
        w0[j] = whh[lane * 16 + j];
        w1[j] = whh[(lane + 32) * 16 + j];
    }
    const bool lo = lane < 16;

    const int sl0 = w * 2, sl1 = w * 2 + 1;
    float pa0[8], pb0[8], pa1[8], pb1[8];
#pragma unroll
    for (int t = 0; t < 8; t++) {
        pa0[t] = sXG[(sl0 * 8 + t) * XGS + lane];
        pb0[t] = sXG[(sl0 * 8 + t) * XGS + lane + 32];
        pa1[t] = sXG[(sl1 * 8 + t) * XGS + lane];
        pb1[t] = sXG[(sl1 * 8 + t) * XGS + lane + 32];
    }
    float h0 = 0.0f, c0 = 0.0f, h1 = 0.0f, c1 = 0.0f;
    float* ob0 = out + ((size_t)blockIdx.x * 16 + sl0) * 128;
    float* ob1 = out + ((size_t)blockIdx.x * 16 + sl1) * 128;

#pragma unroll
    for (int t = 0; t < 8; t++) {
        float ga0 = pa0[t], gb0 = pb0[t];
        float ga1 = pa1[t], gb1 = pb1[t];
#pragma unroll
        for (int j = 0; j < 16; j++) {
            float hj0 = __shfl_sync(0xffffffffu, h0, j);
            float hj1 = __shfl_sync(0xffffffffu, h1, j);
            ga0 = fmaf(w0[j], hj0, ga0);
            gb0 = fmaf(w1[j], hj0, gb0);
            ga1 = fmaf(w0[j], hj1, ga1);
            gb1 = fmaf(w1[j], hj1, gb1);
        }
        float A0, B0, A1, B1;
        if (lo) {
            A0 = sig_(ga0) * tanha_(gb0);  B0 = 0.0f;
            A1 = sig_(ga1) * tanha_(gb1);  B1 = 0.0f;
        } else {
            A0 = sig_(ga0);  B0 = sig_(gb0);
            A1 = sig_(ga1);  B1 = sig_(gb1);
        }
        float f0 = __shfl_sync(0xffffffffu, A0, lane + 16);
        float o0 = __shfl_sync(0xffffffffu, B0, lane + 16);
        float f1 = __shfl_sync(0xffffffffu, A1, lane + 16);
        float o1 = __shfl_sync(0xffffffffu, B1, lane + 16);
        if (lo) {
            c0 = fmaf(f0, c0, A0);
            h0 = o0 * tanha_(c0);
            ob0[t * 16 + lane] = h0;
            c1 = fmaf(f1, c1, A1);
            h1 = o1 * tanha_(c1);
            ob1[t * 16 + lane] = h1;
        }
    }
}

// ---------------- K3: bars bidirectional LSTM, 2 seqs per warp (R10) -------
__global__ __launch_bounds__(256)
void bars_kernel(const float* __restrict__ f_wih,
                 const float* __restrict__ f_whh,
                 const float* __restrict__ f_bih,
                 const float* __restrict__ f_bhh,
                 const float* __restrict__ r_wih,
                 const float* __restrict__ r_whh,
                 const float* __restrict__ r_bih,
                 const float* __restrict__ r_bhh,
                 float* __restrict__ out) {
    __shared__ float s_wih[16][128];
    __shared__ float s_whh[32][128];
    __shared__ float s_b[128];

    const int d = blockIdx.y;
    const float* wih  = d ? r_wih : f_wih;
    const float* whh  = d ? r_whh : f_whh;
    const float* bihp = d ? r_bih : f_bih;
    const float* bhhp = d ? r_bhh : f_bhh;

    for (int i = threadIdx.x; i < 128 * 16; i += blockDim.x) {
        int g = i >> 4, j = i & 15;
        s_wih[j][g] = wih[i];
    }
    for (int i = threadIdx.x; i < 128 * 32; i += blockDim.x) {
        int g = i >> 5, j = i & 31;
        s_whh[j][g] = whh[i];
    }
    if (threadIdx.x < 128) s_b[threadIdx.x] = bihp[threadIdx.x] + bhhp[threadIdx.x];
    __syncthreads();

    const int warp = threadIdx.x >> 5;
    const int lane = threadIdx.x & 31;
    const int n0 = (blockIdx.x * 8 + warp) * 2;
    const int n1 = n0 + 1;

    const float* beats = out;
    float* bars = out + BARS_OUT_OFF;

    float xq0[4], xq1[4];
#pragma unroll
    for (int t = 0; t < 4; t++) {
        xq0[t] = (lane < 16)
            ? beats[(((size_t)n0 * 4 + t) * 8 + 7) * 16 + lane] : 0.0f;
        xq1[t] = (lane < 16)
            ? beats[(((size_t)n1 * 4 + t) * 8 + 7) * 16 + lane] : 0.0f;
    }

    float h0 = 0.0f, c0 = 0.0f, h1 = 0.0f, c1 = 0.0f;
#pragma unroll
    for (int s = 0; s < 4; s++) {
        int t = d ? (3 - s) : s;
        float xv0 = xq0[t], xv1 = xq1[t];

        float gi0 = s_b[lane],      gi1 = gi0;
        float gf0 = s_b[32 + lane], gf1 = gf0;
        float gg0 = s_b[64 + lane], gg1 = gg0;
        float go0 = s_b[96 + lane], go1 = go0;
#pragma unroll
        for (int j = 0; j < 16; j++) {
            float xj0 = __shfl_sync(0xffffffffu, xv0, j);
            float xj1 = __shfl_sync(0xffffffffu, xv1, j);
            float wi = s_wih[j][lane];
            float wf = s_wih[j][32 + lane];
            float wg = s_wih[j][64 + lane];
            float wo = s_wih[j][96 + lane];
            gi0 = fmaf(wi, xj0, gi0);  gi1 = fmaf(wi, xj1, gi1);
            gf0 = fmaf(wf, xj0, gf0);  gf1 = fmaf(wf, xj1, gf1);
            gg0 = fmaf(wg, xj0, gg0);  gg1 = fmaf(wg, xj1, gg1);
            go0 = fmaf(wo, xj0, go0);  go1 = fmaf(wo, xj1, go1);
        }
#pragma unroll
        for (int j = 0; j < 32; j++) {
            float hj0 = __shfl_sync(0xffffffffu, h0, j);
            float hj1 = __shfl_sync(0xffffffffu, h1, j);
            float wi = s_whh[j][lane];
            float wf = s_whh[j][32 + lane];
            float wg = s_whh[j][64 + lane];
            float wo = s_whh[j][96 + lane];
            gi0 = fmaf(wi, hj0, gi0);  gi1 = fmaf(wi, hj1, gi1);
            gf0 = fmaf(wf, hj0, gf0);  gf1 = fmaf(wf, hj1, gf1);
            gg0 = fmaf(wg, hj0, gg0);  gg1 = fmaf(wg, hj1, gg1);
            go0 = fmaf(wo, hj0, go0);  go1 = fmaf(wo, hj1, go1);
        }
        c0 = fmaf(sig_(gf0), c0, sig_(gi0) * tanha_(gg0));
        h0 = sig_(go0) * tanha_(c0);
        c1 = fmaf(sig_(gf1), c1, sig_(gi1) * tanha_(gg1));
        h1 = sig_(go1) * tanha_(c1);
        bars[((size_t)n0 * 4 + t) * 64 + d * 32 + lane] = h0;
        bars[((size_t)n1 * 4 + t) * 64 + d * 32 + lane] = h1;
    }
}

// ---------------- launch ----------------------------------------------------
extern "C" void kernel_launch(void* const* d_in, const int* in_sizes, int n_in,
                              void* d_out, int out_size) {
    const float* channels = (const float*)d_in[0];
    const float* lin_w    = (const float*)d_in[1];
    const float* lin_b    = (const float*)d_in[2];
    const float* b_wih    = (const float*)d_in[3];
    const float* b_whh    = (const float*)d_in[4];
    const float* b_bih    = (const float*)d_in[5];
    const float* b_bhh    = (const float*)d_in[6];
    const float* f_wih    = (const float*)d_in[7];
    const float* f_whh    = (const float*)d_in[8];
    const float* f_bih    = (const float*)d_in[9];
    const float* f_bhh    = (const float*)d_in[10];
    const float* r_wih    = (const float*)d_in[11];
    const float* r_whh    = (const float*)d_in[12];
    const float* r_bih    = (const float*)d_in[13];
    const float* r_bhh    = (const float*)d_in[14];
    float* out = (float*)d_out;

    int prep_n = 128 * KPAD / 4 + 64 * K2PAD + 64;
    prep_kernel<<<(prep_n + 255) / 256, 256>>>(lin_w, b_wih, b_bih, b_bhh);
    gemm1_kernel<<<NROWS / 64, 256>>>(channels, lin_b);
    gemm2_beats<<<NROWS / 128, 256>>>(b_whh, out);
    dim3 g4(NSEQ_R / 16, 2);
    bars_kernel<<<g4, 256>>>(f_wih, f_whh, f_bih, f_bhh,
                             r_wih, r_whh, r_bih, r_bhh, out);
}

// round 17
// speedup vs baseline: 1.1901x; 1.1901x over previous
#include <cuda_runtime.h>
#include <cuda_bf16.h>
#include <cuda_fp16.h>
#include <cstdint>

// ---------------- problem constants ----------------
#define NROWS   32768        // B*BARS*BEATS*FRAC
#define KF      940          // input features (10*2*47)
#define KPAD    960          // K padded to 30 x 32
#define NOUT    100          // linear out
#define K2PAD   112          // padded K for gemm2 (7 x 16)
#define NSEQ_R  1024         // bars LSTM sequences
#define BEATS_OUT_ELEMS (32768 * 16)
#define BARS_OUT_OFF    BEATS_OUT_ELEMS
#define SSTR    40           // smem row stride in b16 elems (80B, 16B-aligned)
#define ARR_ELEMS (128 * SSTR)   // 5120 elems per array
#define XGS     66           // gates smem row stride (floats, even)

typedef unsigned int u32;

// ---------------- scratch ----------------
__device__ __half g_Whf[128 * KPAD];     // linear weight fp16 (permuted)
__device__ __half g_Wbh[64 * K2PAD];     // beats wih fp16 (padded)
__device__ float g_gb[64];
// Xlin as fp16, row stride K2PAD; pad cols [100,112) never written -> stay 0
__device__ __half g_Xh[(size_t)NROWS * K2PAD];

// ---------------- fast activations ----------------
__device__ __forceinline__ float tanha_(float x) {
    float y;
    asm("tanh.approx.f32 %0, %1;" : "=f"(y) : "f"(x));
    return y;
}
__device__ __forceinline__ float sig_(float x) {
    return fmaf(tanha_(0.5f * x), 0.5f, 0.5f);
}

// ---------------- K0: permute weights (fp16, 4/thread), beats weights ------
__global__ void prep_kernel(const float* __restrict__ lin_w,
                            const float* __restrict__ b_wih,
                            const float* __restrict__ b_bih,
                            const float* __restrict__ b_bhh) {
    const int NW4 = 128 * KPAD / 4;   // 30720
    int idx = blockIdx.x * blockDim.x + threadIdx.x;
    if (idx < NW4) {
        int base = idx * 4;
        int o  = base / KPAD;
        int m0 = base % KPAD;
        __half h[4];
#pragma unroll
        for (int e = 0; e < 4; e++) {
            int m = m0 + e;
            float v = 0.0f;
            if (o < NOUT && m < KF) {
                int c10 = m / 94;
                int r   = m % 94;
                int c2  = r / 47;
                int c47 = r % 47;
                v = lin_w[o * KF + c10 * 94 + c47 * 2 + c2];
            }
            h[e] = __float2half_rn(v);
        }
        *(uint2*)(g_Whf + base) = *(uint2*)h;
    } else if (idx < NW4 + 64 * K2PAD) {
        int j = idx - NW4;
        int n = j / K2PAD;
        int k = j % K2PAD;
        float v = (k < NOUT) ? b_wih[n * NOUT + k] : 0.0f;
        g_Wbh[j] = __float2half_rn(v);
    } else if (idx < NW4 + 64 * K2PAD + 64) {
        int j = idx - NW4 - 64 * K2PAD;
        g_gb[j] = b_bih[j] + b_bhh[j];
    }
}

// ---------------- mma helpers ----------------
__device__ __forceinline__ void ldsm4(u32& r0, u32& r1, u32& r2, u32& r3,
                                      u32 addr) {
    asm volatile("ldmatrix.sync.aligned.m8n8.x4.shared.b16 {%0,%1,%2,%3},[%4];"
                 : "=r"(r0), "=r"(r1), "=r"(r2), "=r"(r3) : "r"(addr));
}
__device__ __forceinline__ void ldsm2(u32& r0, u32& r1, u32 addr) {
    asm volatile("ldmatrix.sync.aligned.m8n8.x2.shared.b16 {%0,%1},[%2];"
                 : "=r"(r0), "=r"(r1) : "r"(addr));
}
__device__ __forceinline__ void mma_f16(float* c, const u32* a, const u32* b) {
    asm volatile(
        "mma.sync.aligned.m16n8k16.row.col.f32.f16.f16.f32 "
        "{%0,%1,%2,%3},{%4,%5,%6,%7},{%8,%9},{%0,%1,%2,%3};"
        : "+f"(c[0]), "+f"(c[1]), "+f"(c[2]), "+f"(c[3])
        : "r"(a[0]), "r"(a[1]), "r"(a[2]), "r"(a[3]), "r"(b[0]), "r"(b[1]));
}

// Register staging for the double-buffer prefetch in gemm1.
struct TileRegs {
    float x[16];
    uint4 wh[2];
};

__device__ __forceinline__ void load_tile(int K0, int lc,
                                          const float* __restrict__ xrow,
                                          const __half* __restrict__ wrow,
                                          TileRegs& t) {
#pragma unroll
    for (int j = 0; j < 4; j++) {
        int kb = K0 + lc + j * 4;
        if (kb + 3 < KF) {
            float4 v = *(const float4*)(xrow + K0 + j * 4);
            t.x[j * 4 + 0] = v.x; t.x[j * 4 + 1] = v.y;
            t.x[j * 4 + 2] = v.z; t.x[j * 4 + 3] = v.w;
        } else {
#pragma unroll
            for (int e = 0; e < 4; e++)
                t.x[j * 4 + e] = (kb + e < KF) ? xrow[K0 + j * 4 + e] : 0.0f;
        }
    }
    t.wh[0] = *(const uint4*)(wrow + K0);
    t.wh[1] = *(const uint4*)(wrow + K0 + 8);
}

// Packed: 2x STS.128 for X halves + 2x STS.128 for W.
__device__ __forceinline__ void store_tile(__half* bufbase, int off,
                                           const TileRegs& t) {
    __half* xp = bufbase + off;
    __half* wp = bufbase + ARR_ELEMS + off;
    u32 hw[8];
#pragma unroll
    for (int p = 0; p < 8; p++) {
        __half2 h = __floats2half2_rn(t.x[2 * p], t.x[2 * p + 1]);
        hw[p] = *(u32*)&h;
    }
    *(uint4*)xp       = make_uint4(hw[0], hw[1], hw[2], hw[3]);
    *(uint4*)(xp + 8) = make_uint4(hw[4], hw[5], hw[6], hw[7]);
    *(uint4*)wp       = t.wh[0];
    *(uint4*)(wp + 8) = t.wh[1];
}

// ---------------- K1: Xlin = relu(X @ W^T + b), single-pass fp16 mma -------
// R12 best config: BM=128, 4x2 warp grid with balanced 8/5-nf trim,
// store(it+1) -> LDG(it+2) -> compute(it) -> sync pipeline.
__global__ __launch_bounds__(256, 2)
void gemm1_kernel(const float* __restrict__ X, const float* __restrict__ lin_b) {
    __shared__ __align__(16) __half smem[2 * 2 * ARR_ELEMS];   // 40 KB

    const int tid  = threadIdx.x;
    const int row0 = blockIdx.x * 128;
    const int lr   = tid >> 1;        // 0..127 loader row
    const int lc   = (tid & 1) * 16;  // 0 / 16 loader col base
    const int soff = lr * SSTR + lc;

    const float* xrow = X + (size_t)(row0 + lr) * KF + lc;
    const __half* wrow = g_Whf + lr * KPAD + lc;

    // ldmatrix lane geometry
    const int lane = tid & 31;
    const int w    = tid >> 5;
    const int wm   = w & 3;       // 0..3 -> 32-row quarter
    const int wn   = w >> 2;      // 0..1 -> 64-col half
    const int NF   = wn ? 5 : 8;  // wn1: cols 64..103 only
    const int dra  = ((lane >> 3) & 1) * 8 + (lane & 7);
    const int dca  = (lane >> 4) * 8;
    const int aoff = (wm * 32 + dra) * SSTR + dca;
    const int l2   = lane & 15;
    const int boff = (wn * 64 + (l2 & 7)) * SSTR + (l2 >> 3) * 8;

    const u32 sbase = (u32)__cvta_generic_to_shared(smem);

    float acc[2][8][4];
#pragma unroll
    for (int a = 0; a < 2; a++)
#pragma unroll
        for (int b = 0; b < 8; b++)
#pragma unroll
            for (int c = 0; c < 4; c++) acc[a][b][c] = 0.0f;

    TileRegs t;
    load_tile(0, lc, xrow, wrow, t);
    store_tile(smem, soff, t);            // buffer 0 = tile 0
    load_tile(32, lc, xrow, wrow, t);     // tile 1 staged
    __syncthreads();

    for (int it = 0; it < 30; ++it) {
        if (it + 1 < 30) {
            store_tile(smem + ((it + 1) & 1) * (2 * ARR_ELEMS), soff, t);
            if (it + 2 < 30) load_tile((it + 2) * 32, lc, xrow, wrow, t);
        }

        const u32 cb = sbase + (u32)((it & 1) * (2 * ARR_ELEMS * 2));
#pragma unroll
        for (int kf = 0; kf < 32; kf += 16) {
            u32 af[2][4];
            u32 bf[8][2];
#pragma unroll
            for (int mf = 0; mf < 2; mf++) {
                u32 ea = (u32)(aoff + mf * 16 * SSTR + kf) * 2u;
                ldsm4(af[mf][0], af[mf][1], af[mf][2], af[mf][3], cb + ea);
            }
#pragma unroll
            for (int nf = 0; nf < 8; nf++)
                if (nf < NF) {
                    u32 eb = (u32)(boff + nf * 8 * SSTR + kf) * 2u
                             + (u32)(ARR_ELEMS * 2);
                    ldsm2(bf[nf][0], bf[nf][1], cb + eb);
                }
#pragma unroll
            for (int mf = 0; mf < 2; mf++)
#pragma unroll
                for (int nf = 0; nf < 8; nf++)
                    if (nf < NF)
                        mma_f16(acc[mf][nf], af[mf], bf[nf]);
        }
        __syncthreads();
    }

    // epilogue: relu + bias, fp16, cols < 100
    const int g  = lane >> 2;
    const int t4 = lane & 3;
#pragma unroll
    for (int mf = 0; mf < 2; mf++)
#pragma unroll
        for (int nf = 0; nf < 8; nf++)
            if (nf < NF) {
                int col = wn * 64 + nf * 8 + t4 * 2;
                if (col < NOUT) {
                    float b0 = __ldg(lin_b + col), b1 = __ldg(lin_b + col + 1);
                    int r1 = row0 + wm * 32 + mf * 16 + g;
                    float v0 = fmaxf(acc[mf][nf][0] + b0, 0.0f);
                    float v1 = fmaxf(acc[mf][nf][1] + b1, 0.0f);
                    float v2 = fmaxf(acc[mf][nf][2] + b0, 0.0f);
                    float v3 = fmaxf(acc[mf][nf][3] + b1, 0.0f);
                    *(__half2*)(g_Xh + (size_t)r1 * K2PAD + col) =
                        __floats2half2_rn(v0, v1);
                    *(__half2*)(g_Xh + (size_t)(r1 + 8) * K2PAD + col) =
                        __floats2half2_rn(v2, v3);
                }
            }
}

// ---------------- K2: fused gates GEMM + beats LSTM (R12 best) -------------
__global__ __launch_bounds__(256)
void gemm2_beats(const float* __restrict__ whh, float* __restrict__ out) {
    __shared__ float sXG[128 * XGS];   // 33.8 KB

    const int tid  = threadIdx.x;
    const int lane = tid & 31;
    const int w    = tid >> 5;
    const int wm   = w & 3;
    const int wn   = w >> 2;
    const int g    = lane >> 2;
    const int t4   = lane & 3;
    const int rloc = wm * 32;
    const int row0 = blockIdx.x * 128 + rloc;

    float acc[2][4][4];
#pragma unroll
    for (int a = 0; a < 2; a++)
#pragma unroll
        for (int b = 0; b < 4; b++)
#pragma unroll
            for (int c = 0; c < 4; c++) acc[a][b][c] = 0.0f;

#pragma unroll
    for (int kc = 0; kc < 7; kc++) {
        const int k0 = kc * 16 + t4 * 2;
        u32 af[2][4], bf[4][2];
#pragma unroll
        for (int mf = 0; mf < 2; mf++) {
            size_t base = (size_t)(row0 + mf * 16 + g) * K2PAD + k0;
            af[mf][0] = *(const u32*)(g_Xh + base);
            af[mf][1] = *(const u32*)(g_Xh + base + 8 * K2PAD);
            af[mf][2] = *(const u32*)(g_Xh + base + 8);
            af[mf][3] = *(const u32*)(g_Xh + base + 8 * K2PAD + 8);
        }
#pragma unroll
        for (int nf = 0; nf < 4; nf++) {
            int nbase = (wn * 32 + nf * 8 + g) * K2PAD + k0;
            bf[nf][0] = *(const u32*)(g_Wbh + nbase);
            bf[nf][1] = *(const u32*)(g_Wbh + nbase + 8);
        }
#pragma unroll
        for (int mf = 0; mf < 2; mf++)
#pragma unroll
            for (int nf = 0; nf < 4; nf++)
                mma_f16(acc[mf][nf], af[mf], bf[nf]);
    }

    // gates + bias -> smem
#pragma unroll
    for (int mf = 0; mf < 2; mf++)
#pragma unroll
        for (int nf = 0; nf < 4; nf++) {
            int col = wn * 32 + nf * 8 + t4 * 2;
            float b0 = g_gb[col], b1 = g_gb[col + 1];
            int r = rloc + mf * 16 + g;
            *(float2*)(sXG + r * XGS + col) =
                make_float2(acc[mf][nf][0] + b0, acc[mf][nf][1] + b1);
            *(float2*)(sXG + (r + 8) * XGS + col) =
                make_float2(acc[mf][nf][2] + b0, acc[mf][nf][3] + b1);
        }
    __syncthreads();

    // ---- beats LSTM: warp w handles local seqs 2w, 2w+1 interleaved ----
    float w0[16], w1[16];
#pragma unroll
    for (int j = 0; j < 16; j++) {
        w0[j] = whh[lane * 16 + j];
        w1[j] = whh[(lane + 32) * 16 + j];
    }
    const bool lo = lane < 16;

    const int sl0 = w * 2, sl1 = w * 2 + 1;
    float pa0[8], pb0[8], pa1[8], pb1[8];
#pragma unroll
    for (int t = 0; t < 8; t++) {
        pa0[t] = sXG[(sl0 * 8 + t) * XGS + lane];
        pb0[t] = sXG[(sl0 * 8 + t) * XGS + lane + 32];
        pa1[t] = sXG[(sl1 * 8 + t) * XGS + lane];
        pb1[t] = sXG[(sl1 * 8 + t) * XGS + lane + 32];
    }
    float h0 = 0.0f, c0 = 0.0f, h1 = 0.0f, c1 = 0.0f;
    float* ob0 = out + ((size_t)blockIdx.x * 16 + sl0) * 128;
    float* ob1 = out + ((size_t)blockIdx.x * 16 + sl1) * 128;

#pragma unroll
    for (int t = 0; t < 8; t++) {
        float ga0 = pa0[t], gb0 = pb0[t];
        float ga1 = pa1[t], gb1 = pb1[t];
#pragma unroll
        for (int j = 0; j < 16; j++) {
            float hj0 = __shfl_sync(0xffffffffu, h0, j);
            float hj1 = __shfl_sync(0xffffffffu, h1, j);
            ga0 = fmaf(w0[j], hj0, ga0);
            gb0 = fmaf(w1[j], hj0, gb0);
            ga1 = fmaf(w0[j], hj1, ga1);
            gb1 = fmaf(w1[j], hj1, gb1);
        }
        float A0, B0, A1, B1;
        if (lo) {
            A0 = sig_(ga0) * tanha_(gb0);  B0 = 0.0f;
            A1 = sig_(ga1) * tanha_(gb1);  B1 = 0.0f;
        } else {
            A0 = sig_(ga0);  B0 = sig_(gb0);
            A1 = sig_(ga1);  B1 = sig_(gb1);
        }
        float f0 = __shfl_sync(0xffffffffu, A0, lane + 16);
        float o0 = __shfl_sync(0xffffffffu, B0, lane + 16);
        float f1 = __shfl_sync(0xffffffffu, A1, lane + 16);
        float o1 = __shfl_sync(0xffffffffu, B1, lane + 16);
        if (lo) {
            c0 = fmaf(f0, c0, A0);
            h0 = o0 * tanha_(c0);
            ob0[t * 16 + lane] = h0;
            c1 = fmaf(f1, c1, A1);
            h1 = o1 * tanha_(c1);
            ob1[t * 16 + lane] = h1;
        }
    }
}

// ---------------- K3: bars biLSTM, 2 seqs/warp, direction-ordered prefetch -
// Identical math to the R10 version, but xq[] is prefetched in PROCESSING
// order (s), so the time loop indexes register arrays with the loop counter
// only. The direction-dependent t appears solely in address arithmetic.
__global__ __launch_bounds__(256)
void bars_kernel(const float* __restrict__ f_wih,
                 const float* __restrict__ f_whh,
                 const float* __restrict__ f_bih,
                 const float* __restrict__ f_bhh,
                 const float* __restrict__ r_wih,
                 const float* __restrict__ r_whh,
                 const float* __restrict__ r_bih,
                 const float* __restrict__ r_bhh,
                 float* __restrict__ out) {
    __shared__ float s_wih[16][128];
    __shared__ float s_whh[32][128];
    __shared__ float s_b[128];

    const int d = blockIdx.y;
    const float* wih  = d ? r_wih : f_wih;
    const float* whh  = d ? r_whh : f_whh;
    const float* bihp = d ? r_bih : f_bih;
    const float* bhhp = d ? r_bhh : f_bhh;

    for (int i = threadIdx.x; i < 128 * 16; i += blockDim.x) {
        int g = i >> 4, j = i & 15;
        s_wih[j][g] = wih[i];
    }
    for (int i = threadIdx.x; i < 128 * 32; i += blockDim.x) {
        int g = i >> 5, j = i & 31;
        s_whh[j][g] = whh[i];
    }
    if (threadIdx.x < 128) s_b[threadIdx.x] = bihp[threadIdx.x] + bhhp[threadIdx.x];
    __syncthreads();

    const int warp = threadIdx.x >> 5;
    const int lane = threadIdx.x & 31;
    const int n0 = (blockIdx.x * 8 + warp) * 2;
    const int n1 = n0 + 1;

    const float* beats = out;
    float* bars = out + BARS_OUT_OFF;

    // prefetch in processing order: slot s holds timestep t(s) = d ? 3-s : s
    float xq0[4], xq1[4];
#pragma unroll
    for (int s = 0; s < 4; s++) {
        int tt = d ? (3 - s) : s;
        xq0[s] = (lane < 16)
            ? beats[(((size_t)n0 * 4 + tt) * 8 + 7) * 16 + lane] : 0.0f;
        xq1[s] = (lane < 16)
            ? beats[(((size_t)n1 * 4 + tt) * 8 + 7) * 16 + lane] : 0.0f;
    }

    float h0 = 0.0f, c0 = 0.0f, h1 = 0.0f, c1 = 0.0f;
#pragma unroll
    for (int s = 0; s < 4; s++) {
        const int t = d ? (3 - s) : s;      // address arithmetic only
        float xv0 = xq0[s], xv1 = xq1[s];   // compile-time register index

        float gi0 = s_b[lane],      gi1 = gi0;
        float gf0 = s_b[32 + lane], gf1 = gf0;
        float gg0 = s_b[64 + lane], gg1 = gg0;
        float go0 = s_b[96 + lane], go1 = go0;
#pragma unroll
        for (int j = 0; j < 16; j++) {
            float xj0 = __shfl_sync(0xffffffffu, xv0, j);
            float xj1 = __shfl_sync(0xffffffffu, xv1, j);
            float wi = s_wih[j][lane];
            float wf = s_wih[j][32 + lane];
            float wg = s_wih[j][64 + lane];
            float wo = s_wih[j][96 + lane];
            gi0 = fmaf(wi, xj0, gi0);  gi1 = fmaf(wi, xj1, gi1);
            gf0 = fmaf(wf, xj0, gf0);  gf1 = fmaf(wf, xj1, gf1);
            gg0 = fmaf(wg, xj0, gg0);  gg1 = fmaf(wg, xj1, gg1);
            go0 = fmaf(wo, xj0, go0);  go1 = fmaf(wo, xj1, go1);
        }
#pragma unroll
        for (int j = 0; j < 32; j++) {
            float hj0 = __shfl_sync(0xffffffffu, h0, j);
            float hj1 = __shfl_sync(0xffffffffu, h1, j);
            float wi = s_whh[j][lane];
            float wf = s_whh[j][32 + lane];
            float wg = s_whh[j][64 + lane];
            float wo = s_whh[j][96 + lane];
            gi0 = fmaf(wi, hj0, gi0);  gi1 = fmaf(wi, hj1, gi1);
            gf0 = fmaf(wf, hj0, gf0);  gf1 = fmaf(wf, hj1, gf1);
            gg0 = fmaf(wg, hj0, gg0);  gg1 = fmaf(wg, hj1, gg1);
            go0 = fmaf(wo, hj0, go0);  go1 = fmaf(wo, hj1, go1);
        }
        c0 = fmaf(sig_(gf0), c0, sig_(gi0) * tanha_(gg0));
        h0 = sig_(go0) * tanha_(c0);
        c1 = fmaf(sig_(gf1), c1, sig_(gi1) * tanha_(gg1));
        h1 = sig_(go1) * tanha_(c1);
        bars[((size_t)n0 * 4 + t) * 64 + d * 32 + lane] = h0;
        bars[((size_t)n1 * 4 + t) * 64 + d * 32 + lane] = h1;
    }
}

// ---------------- launch ----------------------------------------------------
extern "C" void kernel_launch(void* const* d_in, const int* in_sizes, int n_in,
                              void* d_out, int out_size) {
    const float* channels = (const float*)d_in[0];
    const float* lin_w    = (const float*)d_in[1];
    const float* lin_b    = (const float*)d_in[2];
    const float* b_wih    = (const float*)d_in[3];
    const float* b_whh    = (const float*)d_in[4];
    const float* b_bih    = (const float*)d_in[5];
    const float* b_bhh    = (const float*)d_in[6];
    const float* f_wih    = (const float*)d_in[7];
    const float* f_whh    = (const float*)d_in[8];
    const float* f_bih    = (const float*)d_in[9];
    const float* f_bhh    = (const float*)d_in[10];
    const float* r_wih    = (const float*)d_in[11];
    const float* r_whh    = (const float*)d_in[12];
    const float* r_bih    = (const float*)d_in[13];
    const float* r_bhh    = (const float*)d_in[14];
    float* out = (float*)d_out;

    int prep_n = 128 * KPAD / 4 + 64 * K2PAD + 64;
    prep_kernel<<<(prep_n + 255) / 256, 256>>>(lin_w, b_wih, b_bih, b_bhh);
    gemm1_kernel<<<NROWS / 128, 256>>>(channels, lin_b);
    gemm2_beats<<<NROWS / 128, 256>>>(b_whh, out);
    dim3 g4(NSEQ_R / 16, 2);
    bars_kernel<<<g4, 256>>>(f_wih, f_whh, f_bih, f_bhh,
                             r_wih, r_whh, r_bih, r_bhh, out);
}